// round 4
// baseline (speedup 1.0000x reference)
#include <cuda_runtime.h>

// out[b] = sum_k x[b,k] * S[k],  S[k] = sum_h W[h,k]   (scale 0.5*2.0 == 1.0)
// Pipelined across NCHUNK k-chunks on two streams: colsum(c) -> matvec(c),
// so the two HBM streams (W and x) overlap in the steady state.

#define BATCH 4096
#define IN    4096
#define HID   4096
#define NCHUNK 4
#define CK   (IN / NCHUNK)   // 1024 columns per chunk
#define CK4  (CK / 4)        // 256 float4 per chunk

__device__ __align__(16) float g_S[IN];

// Sum rows of W over one k-chunk. block=256 (covers all 256 float4 of the chunk),
// grid.x = HID/16 row-groups. MLP=16 per thread.
__global__ void __launch_bounds__(256) colsum_chunk(const float* __restrict__ W, int c) {
    const int ROWS = 16;
    int k4 = threadIdx.x;               // float4 index within chunk
    int h0 = blockIdx.x * ROWS;

    const float4* Wv = reinterpret_cast<const float4*>(W);
    long base = (long)h0 * (IN / 4) + c * CK4 + k4;

    float4 acc = make_float4(0.f, 0.f, 0.f, 0.f);
    #pragma unroll
    for (int r = 0; r < ROWS; r++) {
        float4 v = __ldcs(&Wv[base + (long)r * (IN / 4)]);
        acc.x += v.x; acc.y += v.y; acc.z += v.z; acc.w += v.w;
    }
    float* dst = &g_S[c * CK + k4 * 4];
    asm volatile("red.global.add.v4.f32 [%0], {%1, %2, %3, %4};"
                 :: "l"(dst), "f"(acc.x), "f"(acc.y), "f"(acc.z), "f"(acc.w)
                 : "memory");
}

// Warp-per-row partial dot over one k-chunk; accumulate into out[b].
// 8 fully-unrolled iterations -> 8 independent x-loads in flight per lane.
__global__ void __launch_bounds__(128) matvec_chunk(const float* __restrict__ x,
                                                    float* __restrict__ out, int c) {
    int row  = (blockIdx.x * blockDim.x + threadIdx.x) >> 5;
    int lane = threadIdx.x & 31;

    const float4* xv = reinterpret_cast<const float4*>(x) + (long)row * (IN / 4) + c * CK4;
    const float4* Sv = reinterpret_cast<const float4*>(g_S) + c * CK4;

    float a0 = 0.f, a1 = 0.f, a2 = 0.f, a3 = 0.f;
    #pragma unroll
    for (int i = 0; i < CK4 / 32; i++) {       // 8 iterations
        int idx = lane + i * 32;
        float4 xx = __ldcs(&xv[idx]);
        float4 ss = Sv[idx];                   // 4 KB chunk of S: L1/L2-hot
        a0 = fmaf(xx.x, ss.x, a0);
        a1 = fmaf(xx.y, ss.y, a1);
        a2 = fmaf(xx.z, ss.z, a2);
        a3 = fmaf(xx.w, ss.w, a3);
    }
    float sum = (a0 + a1) + (a2 + a3);

    #pragma unroll
    for (int off = 16; off > 0; off >>= 1)
        sum += __shfl_xor_sync(0xFFFFFFFFu, sum, off);

    if (lane == 0) atomicAdd(&out[row], sum);  // 4096 distinct addresses per chunk
}

extern "C" void kernel_launch(void* const* d_in, const int* in_sizes, int n_in,
                              void* d_out, int out_size) {
    const float* x = (const float*)d_in[0];
    const float* W = (const float*)d_in[1];
    float* out = (float*)d_out;

    static cudaStream_t sA = nullptr, sB = nullptr;
    static cudaEvent_t evFork, evCS[NCHUNK], evA, evB;
    if (!sA) {
        cudaStreamCreateWithFlags(&sA, cudaStreamNonBlocking);
        cudaStreamCreateWithFlags(&sB, cudaStreamNonBlocking);
        cudaEventCreateWithFlags(&evFork, cudaEventDisableTiming);
        for (int i = 0; i < NCHUNK; i++)
            cudaEventCreateWithFlags(&evCS[i], cudaEventDisableTiming);
        cudaEventCreateWithFlags(&evA, cudaEventDisableTiming);
        cudaEventCreateWithFlags(&evB, cudaEventDisableTiming);
    }

    // Zero S and out (out accumulates across chunks).
    void* s_ptr = nullptr;
    cudaGetSymbolAddress(&s_ptr, g_S);
    cudaMemsetAsync(s_ptr, 0, IN * sizeof(float), 0);
    cudaMemsetAsync(out, 0, BATCH * sizeof(float), 0);

    // Fork both worker streams off the capture-origin stream.
    cudaEventRecord(evFork, 0);
    cudaStreamWaitEvent(sA, evFork, 0);
    cudaStreamWaitEvent(sB, evFork, 0);

    for (int c = 0; c < NCHUNK; c++) {
        colsum_chunk<<<HID / 16, 256, 0, sA>>>(W, c);
        cudaEventRecord(evCS[c], sA);
        cudaStreamWaitEvent(sB, evCS[c], 0);
        matvec_chunk<<<(BATCH * 32) / 128, 128, 0, sB>>>(x, out, c);
    }

    // Join both streams back to the origin stream.
    cudaEventRecord(evA, sA);
    cudaEventRecord(evB, sB);
    cudaStreamWaitEvent((cudaStream_t)0, evA, 0);
    cudaStreamWaitEvent((cudaStream_t)0, evB, 0);
}

// round 6
// speedup vs baseline: 1.3674x; 1.3674x over previous
#include <cuda_runtime.h>

// out[b] = sum_k x[b,k] * S[k],  S[k] = sum_h W[h,k]   (scale 0.5*2.0 == 1.0)
// Two HBM-bound passes. Limiter last round: register-starved MLP (regs=40
// could not hold 8 in-flight float4). Fix: S in smem, 8 front-batched loads.

#define BATCH 4096
#define IN    4096
#define HID   4096

__device__ __align__(16) float g_S[IN];

// Column-sum of W [HID, IN]. grid=(4, 256), block=256, 16 rows per CTA.
// Loads issued in front-batched groups of 8 for sustained MLP=8.
__global__ void __launch_bounds__(256, 4) colsum_kernel(const float* __restrict__ W) {
    int k4 = blockIdx.x * blockDim.x + threadIdx.x;   // float4 index along k
    int h0 = blockIdx.y * 16;

    const float4* Wv = reinterpret_cast<const float4*>(W);
    const int stride4 = IN / 4;
    long base = (long)h0 * stride4 + k4;

    float4 acc = make_float4(0.f, 0.f, 0.f, 0.f);
    #pragma unroll
    for (int g = 0; g < 2; g++) {
        float4 v[8];
        #pragma unroll
        for (int r = 0; r < 8; r++)
            v[r] = __ldcs(&Wv[base + (long)(g * 8 + r) * stride4]);
        #pragma unroll
        for (int r = 0; r < 8; r++) {
            acc.x += v[r].x; acc.y += v[r].y; acc.z += v[r].z; acc.w += v[r].w;
        }
    }
    float* dst = &g_S[k4 * 4];
    asm volatile("red.global.add.v4.f32 [%0], {%1, %2, %3, %4};"
                 :: "l"(dst), "f"(acc.x), "f"(acc.y), "f"(acc.z), "f"(acc.w)
                 : "memory");
}

// Persistent matvec. S cached in smem; 2 rows per CTA-iteration with
// 8 front-batched x-loads per thread. Direct stores (CTA owns its rows).
__global__ void __launch_bounds__(256, 4) matvec_kernel(const float* __restrict__ x,
                                                        float* __restrict__ out) {
    __shared__ float sS[IN];
    __shared__ float red0[8], red1[8];

    const int tid  = threadIdx.x;
    const int lane = tid & 31;
    const int wid  = tid >> 5;

    // Preload S (L2-hot, 16 KB).
    #pragma unroll
    for (int i = tid; i < IN / 4; i += 256)
        reinterpret_cast<float4*>(sS)[i] = reinterpret_cast<const float4*>(g_S)[i];
    __syncthreads();

    const float4* xv = reinterpret_cast<const float4*>(x);
    const float4* Ss = reinterpret_cast<const float4*>(sS);

    for (int b = blockIdx.x * 2; b < BATCH; b += gridDim.x * 2) {
        long r0 = (long)b * (IN / 4);
        long r1 = r0 + (IN / 4);

        // Front-batch all 8 DRAM loads (2 rows x 4 float4 per thread).
        float4 v0[4], v1[4];
        #pragma unroll
        for (int j = 0; j < 4; j++) v0[j] = __ldcs(&xv[r0 + tid + j * 256]);
        #pragma unroll
        for (int j = 0; j < 4; j++) v1[j] = __ldcs(&xv[r1 + tid + j * 256]);

        float s0 = 0.f, s1 = 0.f;
        #pragma unroll
        for (int j = 0; j < 4; j++) {
            float4 ss = Ss[tid + j * 256];
            s0 = fmaf(v0[j].x, ss.x, s0); s0 = fmaf(v0[j].y, ss.y, s0);
            s0 = fmaf(v0[j].z, ss.z, s0); s0 = fmaf(v0[j].w, ss.w, s0);
            s1 = fmaf(v1[j].x, ss.x, s1); s1 = fmaf(v1[j].y, ss.y, s1);
            s1 = fmaf(v1[j].z, ss.z, s1); s1 = fmaf(v1[j].w, ss.w, s1);
        }

        #pragma unroll
        for (int off = 16; off > 0; off >>= 1) {
            s0 += __shfl_xor_sync(0xFFFFFFFFu, s0, off);
            s1 += __shfl_xor_sync(0xFFFFFFFFu, s1, off);
        }
        if (lane == 0) { red0[wid] = s0; red1[wid] = s1; }
        __syncthreads();
        if (wid == 0 && lane < 8) {
            float a = red0[lane], c = red1[lane];
            #pragma unroll
            for (int off = 4; off > 0; off >>= 1) {
                a += __shfl_xor_sync(0xFFu, a, off);
                c += __shfl_xor_sync(0xFFu, c, off);
            }
            if (lane == 0) { out[b] = a; out[b + 1] = c; }
        }
        __syncthreads();
    }
}

extern "C" void kernel_launch(void* const* d_in, const int* in_sizes, int n_in,
                              void* d_out, int out_size) {
    const float* x = (const float*)d_in[0];
    const float* W = (const float*)d_in[1];
    float* out = (float*)d_out;

    void* s_ptr = nullptr;
    cudaGetSymbolAddress(&s_ptr, g_S);
    cudaMemsetAsync(s_ptr, 0, IN * sizeof(float));

    // colsum: 1024 CTAs, 16 rows each, MLP=8 front-batched
    dim3 cs_grid(IN / (256 * 4), HID / 16);
    colsum_kernel<<<cs_grid, 256>>>(W);

    // matvec: persistent 4 CTAs/SM
    matvec_kernel<<<148 * 4, 256>>>(x, out);
}